// round 6
// baseline (speedup 1.0000x reference)
#include <cuda_runtime.h>
#include <mma.h>
#include <math.h>
#include <stdint.h>

#define NROWS 8192
#define DIM 512

__device__ float g_Q [NROWS*DIM];
__device__ float g_K [NROWS*DIM];
__device__ float g_V [NROWS*DIM];
__device__ float g_XR[NROWS*DIM];
__device__ float g_H [NROWS*DIM];

__device__ __forceinline__ float tf32r(float v) { return nvcuda::wmma::__float_to_tf32(v); }

__device__ __forceinline__ void mma8(float* c, const float* a, const float* b) {
    asm volatile("mma.sync.aligned.m16n8k8.row.col.f32.tf32.tf32.f32 "
        "{%0,%1,%2,%3}, {%4,%5,%6,%7}, {%8,%9}, {%0,%1,%2,%3};"
        : "+f"(c[0]), "+f"(c[1]), "+f"(c[2]), "+f"(c[3])
        : "r"(__float_as_uint(a[0])), "r"(__float_as_uint(a[1])),
          "r"(__float_as_uint(a[2])), "r"(__float_as_uint(a[3])),
          "r"(__float_as_uint(b[0])), "r"(__float_as_uint(b[1])));
}

__device__ __forceinline__ void cpa16(uint32_t dst, const void* src) {
    asm volatile("cp.async.cg.shared.global [%0], [%1], 16;" :: "r"(dst), "l"(src));
}
#define CPA_COMMIT() asm volatile("cp.async.commit_group;" ::: "memory")
#define CPA_WAIT0()  asm volatile("cp.async.wait_group 0;"  ::: "memory")

// ===========================================================================
// Retention: O = (D .* (Q K^T)) @ V.  CTA = 64 Q-rows, 512 thr (16 warps).
// j-chunks of 128.
//   QK: S 64x128, warp grid 2(m) x 8(n), warp tile 32x16.
//   SV: O 64x512, warp grid 2(m) x 8(n), warp tile 32x64.
// SMEM (floats): Qf[64][516]=33024 | region1 = Ks[2][128][36]=9216 (QK)
//   aliased with Ss[64][132]=8448 (D-phase/SV) | region2 = Ds[64][132]=8448
//   (QK/D-phase, cp.async-prefetched) aliased with Vs[2][8][520]=8320 (SV).
// Total 50688 floats = 202752 B.
// ===========================================================================
#define RET_SMEM 202752

__global__ void __launch_bounds__(512, 1) retention_mma(
    const float* __restrict__ Q, const float* __restrict__ K,
    const float* __restrict__ V, const float* __restrict__ D,
    float* __restrict__ O)
{
    extern __shared__ float sm[];
    float (*Qf)[516]    = (float(*)[516])sm;                 // 33024 fl
    float* reg1 = sm + 33024;                                // 9216 fl
    float* reg2 = sm + 42240;                                // 8448 fl
    float (*Ks)[128][36] = (float(*)[128][36])reg1;          // QK phase
    float (*Ss)[132]     = (float(*)[132])    reg1;          // D/SV phase
    float (*Ds)[132]     = (float(*)[132])    reg2;          // QK/D phase
    float (*Vs)[8][520]  = (float(*)[8][520])reg2;           // SV phase

    const int tid = threadIdx.x;
    const int lane = tid & 31, w = tid >> 5;
    const int wm = w >> 3, wn = w & 7;       // 2 x 8 warp grid
    const int qr = lane >> 2, qc = lane & 3;
    const int i0 = blockIdx.x * 64;

    const uint32_t sKs = (uint32_t)__cvta_generic_to_shared(reg1);
    const uint32_t sDs = (uint32_t)__cvta_generic_to_shared(reg2);
    const uint32_t sVs = sDs;

    // Loader indices
    const int dk_r = tid >> 3, dk_c = (tid & 7) * 4;     // K: 2 passes of 64 rows
    const int dd_r = tid >> 5, dd_c = (tid & 31) * 4;    // D: 4 passes of 16 rows
    const int dv_r = tid >> 7, dv_c = (tid & 127) * 4;   // V: 2 passes of 4 rows

    // Q tile resident (producer already tf32-rounded)
    #pragma unroll
    for (int p = 0; p < 16; p++) {
        int idx = tid + p*512, r = idx >> 7, c4 = (idx & 127) * 4;
        *(float4*)&Qf[r][c4] = *(const float4*)&Q[(size_t)(i0 + r)*DIM + c4];
    }

    float o[2][8][4];
    #pragma unroll
    for (int f = 0; f < 2; f++)
        #pragma unroll
        for (int g = 0; g < 8; g++)
            #pragma unroll
            for (int e = 0; e < 4; e++) o[f][g][e] = 0.f;

    __syncthreads();

    #pragma unroll 1
    for (int j0 = 0; j0 < NROWS; j0 += 128) {
        // ---- issue D tile prefetch (DRAM; overlaps whole QK phase) ----
        #pragma unroll
        for (int p = 0; p < 4; p++) {
            int r = dd_r + p*16;
            cpa16(sDs + (uint32_t)(r*132 + dd_c)*4u,
                  &D[(size_t)(i0 + r)*NROWS + j0 + dd_c]);
        }
        CPA_COMMIT();
        // ---- issue K stage 0 ----
        #pragma unroll
        for (int p = 0; p < 2; p++) {
            int r = dk_r + p*64;
            cpa16(sKs + (uint32_t)(r*36 + dk_c)*4u,
                  &K[(size_t)(j0 + r)*DIM + dk_c]);
        }
        CPA_COMMIT();

        // ---------------- QK:  S = Q @ K[j0:j0+128]^T ----------------
        float s[2][2][4];
        #pragma unroll
        for (int f = 0; f < 2; f++)
            #pragma unroll
            for (int g = 0; g < 2; g++)
                #pragma unroll
                for (int e = 0; e < 4; e++) s[f][g][e] = 0.f;

        #pragma unroll 1
        for (int kc = 0; kc < 16; kc++) {
            const int buf = kc & 1;
            CPA_WAIT0();
            __syncthreads();
            if (kc < 15) {
                #pragma unroll
                for (int p = 0; p < 2; p++) {
                    int r = dk_r + p*64;
                    cpa16(sKs + (uint32_t)((buf^1)*128*36 + r*36 + dk_c)*4u,
                          &K[(size_t)(j0 + r)*DIM + (kc+1)*32 + dk_c]);
                }
                CPA_COMMIT();
            }
            #pragma unroll
            for (int k8 = 0; k8 < 4; k8++) {
                const int kq = kc*32 + k8*8 + qc;
                const int kk = k8*8 + qc;
                float a[2][4];
                #pragma unroll
                for (int f = 0; f < 2; f++) {
                    int rb = wm*32 + f*16 + qr;
                    a[f][0] = Qf[rb][kq];     a[f][1] = Qf[rb+8][kq];
                    a[f][2] = Qf[rb][kq+4];   a[f][3] = Qf[rb+8][kq+4];
                }
                #pragma unroll
                for (int g = 0; g < 2; g++) {
                    int nb = wn*16 + g*8 + qr;
                    float b[2] = { Ks[buf][nb][kk], Ks[buf][nb][kk+4] };
                    mma8(s[0][g], a[0], b);
                    mma8(s[1][g], a[1], b);
                }
            }
        }
        __syncthreads();   // QK reads of Ks done -> Ss (aliased) may be written

        // ------- D-phase: Ss = tf32(S .* Ds)  (Ds already in SMEM) -------
        #pragma unroll
        for (int f = 0; f < 2; f++)
            #pragma unroll
            for (int g = 0; g < 2; g++) {
                int r = wm*32 + f*16 + qr;
                int c = wn*16 + g*8 + 2*qc;
                float2 d0 = *(float2*)&Ds[r][c];
                float2 d1 = *(float2*)&Ds[r+8][c];
                float2 o0 = make_float2(tf32r(s[f][g][0]*d0.x), tf32r(s[f][g][1]*d0.y));
                float2 o1 = make_float2(tf32r(s[f][g][2]*d1.x), tf32r(s[f][g][3]*d1.y));
                *(float2*)&Ss[r][c]   = o0;
                *(float2*)&Ss[r+8][c] = o1;
            }
        __syncthreads();   // Ds reads done -> Vs (aliased) may be written

        // ---- issue V stage 0 ----
        #pragma unroll
        for (int p = 0; p < 2; p++) {
            int r = dv_r + p*4;
            cpa16(sVs + (uint32_t)(r*520 + dv_c)*4u,
                  &V[(size_t)(j0 + r)*DIM + dv_c]);
        }
        CPA_COMMIT();

        // ------------- SV:  O += Ss @ V[j0:j0+128]  (16 stages) -------------
        #pragma unroll 1
        for (int st = 0; st < 16; st++) {
            const int buf = st & 1;
            CPA_WAIT0();
            __syncthreads();
            if (st < 15) {
                #pragma unroll
                for (int p = 0; p < 2; p++) {
                    int r = dv_r + p*4;
                    cpa16(sVs + (uint32_t)((buf^1)*8*520 + r*520 + dv_c)*4u,
                          &V[(size_t)(j0 + (st+1)*8 + r)*DIM + dv_c]);
                }
                CPA_COMMIT();
            }
            const int k = st*8 + qc;
            float a[2][4];
            #pragma unroll
            for (int f = 0; f < 2; f++) {
                int rb = wm*32 + f*16 + qr;
                a[f][0] = Ss[rb][k];     a[f][1] = Ss[rb+8][k];
                a[f][2] = Ss[rb][k+4];   a[f][3] = Ss[rb+8][k+4];
            }
            #pragma unroll
            for (int g = 0; g < 8; g++) {
                int n = wn*64 + g*8 + qr;
                float b[2] = { Vs[buf][qc][n], Vs[buf][qc+4][n] };
                mma8(o[0][g], a[0], b);
                mma8(o[1][g], a[1], b);
            }
        }
        __syncthreads();   // SV reads of Ss/Vs done before next chunk's D/K issue
    }

    // ---------------- epilogue ----------------
    #pragma unroll
    for (int f = 0; f < 2; f++)
        #pragma unroll
        for (int g = 0; g < 8; g++) {
            int r = i0 + wm*32 + f*16 + qr;
            int c = wn*64 + g*8 + 2*qc;
            *(float2*)&O[(size_t)r*DIM + c]       = make_float2(o[f][g][0], o[f][g][1]);
            *(float2*)&O[(size_t)(r + 8)*DIM + c] = make_float2(o[f][g][2], o[f][g][3]);
        }
}

// ===========================================================================
// Small GEMMs (tf32x3): C = act(A @ B + bias).  BM=128, BN=64, BK=32.
// 256 thr, warps 4(m) x 2(n), warp tile 32x32.  hi/lo split at SMEM store.
// ===========================================================================
#define GEMM_SMEM 55296

template<int ACT, int ROUND>
__global__ void __launch_bounds__(256) gemm_x3(
    const float* __restrict__ A, const float* __restrict__ B,
    const float* __restrict__ bias, float* __restrict__ C)
{
    extern __shared__ float sm[];
    float (*Ah)[36] = (float(*)[36]) sm;
    float (*Al)[36] = (float(*)[36])(sm + 4608);
    float (*Bh)[72] = (float(*)[72])(sm + 9216);
    float (*Bl)[72] = (float(*)[72])(sm + 11520);

    const int tid = threadIdx.x;
    const int lane = tid & 31, w = tid >> 5;
    const int wm = w >> 1, wn = w & 1;
    const int qr = lane >> 2, qc = lane & 3;
    const int bm = blockIdx.x * 128, bn = blockIdx.y * 64;

    float acc[2][4][4];
    #pragma unroll
    for (int f = 0; f < 2; f++)
        #pragma unroll
        for (int g = 0; g < 4; g++)
            #pragma unroll
            for (int e = 0; e < 4; e++) acc[f][g][e] = 0.f;

    float4 ap[4]; float4 bp[2];
    #pragma unroll
    for (int p = 0; p < 4; p++) {
        int idx = tid + p*256, r = idx >> 3, c4 = (idx & 7) * 4;
        ap[p] = *(const float4*)&A[(size_t)(bm + r)*DIM + c4];
    }
    #pragma unroll
    for (int p = 0; p < 2; p++) {
        int idx = tid + p*256, r = idx >> 4, c4 = (idx & 15) * 4;
        bp[p] = *(const float4*)&B[(size_t)r*DIM + bn + c4];
    }

    #pragma unroll 1
    for (int kc = 0; kc < 16; kc++) {
        #pragma unroll
        for (int p = 0; p < 4; p++) {
            int idx = tid + p*256, r = idx >> 3, c4 = (idx & 7) * 4;
            float vv[4] = {ap[p].x, ap[p].y, ap[p].z, ap[p].w};
            #pragma unroll
            for (int e = 0; e < 4; e++) {
                float h = tf32r(vv[e]);
                Ah[r][c4+e] = h;
                Al[r][c4+e] = tf32r(vv[e] - h);
            }
        }
        #pragma unroll
        for (int p = 0; p < 2; p++) {
            int idx = tid + p*256, r = idx >> 4, c4 = (idx & 15) * 4;
            float vv[4] = {bp[p].x, bp[p].y, bp[p].z, bp[p].w};
            #pragma unroll
            for (int e = 0; e < 4; e++) {
                float h = tf32r(vv[e]);
                Bh[r][c4+e] = h;
                Bl[r][c4+e] = tf32r(vv[e] - h);
            }
        }
        __syncthreads();
        if (kc < 15) {
            #pragma unroll
            for (int p = 0; p < 4; p++) {
                int idx = tid + p*256, r = idx >> 3, c4 = (idx & 7) * 4;
                ap[p] = *(const float4*)&A[(size_t)(bm + r)*DIM + (kc+1)*32 + c4];
            }
            #pragma unroll
            for (int p = 0; p < 2; p++) {
                int idx = tid + p*256, r = idx >> 4, c4 = (idx & 15) * 4;
                bp[p] = *(const float4*)&B[(size_t)((kc+1)*32 + r)*DIM + bn + c4];
            }
        }
        #pragma unroll
        for (int k8 = 0; k8 < 4; k8++) {
            const int kk = k8*8 + qc;
            float ah[2][4], al[2][4];
            #pragma unroll
            for (int f = 0; f < 2; f++) {
                int rb = wm*32 + f*16 + qr;
                ah[f][0] = Ah[rb][kk];   ah[f][1] = Ah[rb+8][kk];
                ah[f][2] = Ah[rb][kk+4]; ah[f][3] = Ah[rb+8][kk+4];
                al[f][0] = Al[rb][kk];   al[f][1] = Al[rb+8][kk];
                al[f][2] = Al[rb][kk+4]; al[f][3] = Al[rb+8][kk+4];
            }
            #pragma unroll
            for (int g = 0; g < 4; g++) {
                int n = wn*32 + g*8 + qr;
                float bh[2] = { Bh[kk][n], Bh[kk+4][n] };
                float bl[2] = { Bl[kk][n], Bl[kk+4][n] };
                #pragma unroll
                for (int f = 0; f < 2; f++) {
                    mma8(acc[f][g], ah[f], bh);
                    mma8(acc[f][g], al[f], bh);
                    mma8(acc[f][g], ah[f], bl);
                }
            }
        }
        __syncthreads();
    }

    #pragma unroll
    for (int f = 0; f < 2; f++)
        #pragma unroll
        for (int g = 0; g < 4; g++) {
            int r = bm + wm*32 + f*16 + qr;
            int c = bn + wn*32 + g*8 + 2*qc;
            float2 bb = *(const float2*)&bias[c];
            float v0 = acc[f][g][0] + bb.x, v1 = acc[f][g][1] + bb.y;
            float v2 = acc[f][g][2] + bb.x, v3 = acc[f][g][3] + bb.y;
            if (ACT == 1) {
                v0 = 0.5f*v0*(1.f + erff(v0*0.70710678118654752f));
                v1 = 0.5f*v1*(1.f + erff(v1*0.70710678118654752f));
                v2 = 0.5f*v2*(1.f + erff(v2*0.70710678118654752f));
                v3 = 0.5f*v3*(1.f + erff(v3*0.70710678118654752f));
            }
            if (ROUND == 1) { v0 = tf32r(v0); v1 = tf32r(v1); v2 = tf32r(v2); v3 = tf32r(v3); }
            *(float2*)&C[(size_t)r*DIM + c]       = make_float2(v0, v1);
            *(float2*)&C[(size_t)(r + 8)*DIM + c] = make_float2(v2, v3);
        }
}

// ---------------------------------------------------------------------------
__global__ void groupnorm_kernel(float* __restrict__ out,
                                 const float* __restrict__ gamma,
                                 const float* __restrict__ beta)
{
    __shared__ float buf[512];
    __shared__ float smu[16], siv[16];
    const int row = blockIdx.x;
    const int tid = threadIdx.x;
    float* p = out + (size_t)row * DIM;
    buf[tid]       = p[tid];
    buf[tid + 256] = p[tid + 256];
    __syncthreads();
    if (tid < 16) {
        float sx = 0.f, s2 = 0.f;
        #pragma unroll
        for (int c = 0; c < 32; c++) { float v = buf[tid*32 + c]; sx += v; s2 += v*v; }
        float mu  = sx * (1.f/32.f);
        float var = s2 * (1.f/32.f) - mu*mu;
        smu[tid] = mu;
        siv[tid] = rsqrtf(var + 1e-5f);
    }
    __syncthreads();
    #pragma unroll
    for (int q = 0; q < 2; q++) {
        int c = tid + q*256;
        int g = c >> 5;
        p[c] = (buf[c] - smu[g]) * siv[g] * gamma[c] + beta[c];
    }
}

// ---------------------------------------------------------------------------
extern "C" void kernel_launch(void* const* d_in, const int* in_sizes, int n_in,
                              void* d_out, int out_size)
{
    const float* x     = (const float*)d_in[0];
    const float* D     = (const float*)d_in[1];
    const float* Wq    = (const float*)d_in[2];
    const float* bq    = (const float*)d_in[3];
    const float* Wk    = (const float*)d_in[4];
    const float* bk    = (const float*)d_in[5];
    const float* Wv    = (const float*)d_in[6];
    const float* bv    = (const float*)d_in[7];
    const float* Wf    = (const float*)d_in[8];
    const float* bf    = (const float*)d_in[9];
    const float* Wp    = (const float*)d_in[10];
    const float* bp    = (const float*)d_in[11];
    const float* gamma = (const float*)d_in[12];
    const float* beta  = (const float*)d_in[13];
    float* out = (float*)d_out;

    float *Q, *K, *V, *XR, *H;
    cudaGetSymbolAddress((void**)&Q,  g_Q);
    cudaGetSymbolAddress((void**)&K,  g_K);
    cudaGetSymbolAddress((void**)&V,  g_V);
    cudaGetSymbolAddress((void**)&XR, g_XR);
    cudaGetSymbolAddress((void**)&H,  g_H);

    cudaFuncSetAttribute(gemm_x3<0,1>,
                         cudaFuncAttributeMaxDynamicSharedMemorySize, GEMM_SMEM);
    cudaFuncSetAttribute(gemm_x3<1,0>,
                         cudaFuncAttributeMaxDynamicSharedMemorySize, GEMM_SMEM);
    cudaFuncSetAttribute(gemm_x3<0,0>,
                         cudaFuncAttributeMaxDynamicSharedMemorySize, GEMM_SMEM);
    cudaFuncSetAttribute(retention_mma,
                         cudaFuncAttributeMaxDynamicSharedMemorySize, RET_SMEM);

    dim3 gs(NROWS/128, DIM/64);    // 64 x 8
    gemm_x3<0,1><<<gs, 256, GEMM_SMEM>>>(x, Wq, bq, Q);
    gemm_x3<0,1><<<gs, 256, GEMM_SMEM>>>(x, Wk, bk, K);
    gemm_x3<0,1><<<gs, 256, GEMM_SMEM>>>(x, Wv, bv, V);

    retention_mma<<<NROWS/64, 512, RET_SMEM>>>(Q, K, V, D, XR);

    gemm_x3<1,0><<<gs, 256, GEMM_SMEM>>>(XR, Wf, bf, H);   // exact GELU
    gemm_x3<0,0><<<gs, 256, GEMM_SMEM>>>(H,  Wp, bp, out);

    groupnorm_kernel<<<NROWS, 256>>>(out, gamma, beta);
}

// round 7
// speedup vs baseline: 1.1858x; 1.1858x over previous
#include <cuda_runtime.h>
#include <mma.h>
#include <math.h>
#include <stdint.h>

#define NROWS 8192
#define DIM 512

__device__ float g_Q [NROWS*DIM];
__device__ float g_K [NROWS*DIM];
__device__ float g_V [NROWS*DIM];
__device__ float g_XR[NROWS*DIM];
__device__ float g_H [NROWS*DIM];

__device__ __forceinline__ float tf32r(float v) { return nvcuda::wmma::__float_to_tf32(v); }

__device__ __forceinline__ void mma8(float* c, const float* a, const float* b) {
    asm volatile("mma.sync.aligned.m16n8k8.row.col.f32.tf32.tf32.f32 "
        "{%0,%1,%2,%3}, {%4,%5,%6,%7}, {%8,%9}, {%0,%1,%2,%3};"
        : "+f"(c[0]), "+f"(c[1]), "+f"(c[2]), "+f"(c[3])
        : "r"(__float_as_uint(a[0])), "r"(__float_as_uint(a[1])),
          "r"(__float_as_uint(a[2])), "r"(__float_as_uint(a[3])),
          "r"(__float_as_uint(b[0])), "r"(__float_as_uint(b[1])));
}

__device__ __forceinline__ void cpa16(uint32_t dst, const void* src) {
    asm volatile("cp.async.cg.shared.global [%0], [%1], 16;" :: "r"(dst), "l"(src));
}
#define CPA_COMMIT() asm volatile("cp.async.commit_group;" ::: "memory")
#define CPA_WAIT0()  asm volatile("cp.async.wait_group 0;"  ::: "memory")
#define CPA_WAIT1()  asm volatile("cp.async.wait_group 1;"  ::: "memory")

// ===========================================================================
// Retention: O = (D .* (Q K^T)) @ V.  CTA = 64 Q-rows, 512 thr (16 warps).
// j-chunk 256.
//   QK: S 64x256, warp grid 2(m) x 8(n), warp tile 32x32. K-dim staged by 32,
//       3-deep cp.async ring; each stage group also carries 4 rows of D tile.
//   SV: O 64x512, warp grid 2(m) x 8(n), warp tile 32x64. 32 stages of 8 V-rows,
//       3-deep ring.
// SMEM (floats): ring 3 x (Qs 64x36 + Ks 256x36) = 34560, overlaid by
//   Ss[64][260]=16640 after QK.  Ds[64][260]=16640, overlaid by Vs[3][8][520]
//   =12480 after D-phase.  Total 51200 fl = 204800 B.
// ===========================================================================
#define STG_FL   11520              // floats per ring stage (Qs+Ks)
#define RING_FL  (3*STG_FL)         // 34560
#define RET_SMEM ((RING_FL + 16640) * 4)   // 204800 B

__global__ void __launch_bounds__(512, 1) retention_mma(
    const float* __restrict__ Q, const float* __restrict__ K,
    const float* __restrict__ V, const float* __restrict__ D,
    float* __restrict__ O)
{
    extern __shared__ float sm[];
    float* ring = sm;                                  // QK stages
    float (*Ss)[260]    = (float(*)[260])sm;           // aliases ring
    float (*Ds)[260]    = (float(*)[260])(sm + RING_FL);
    float (*Vs)[8][520] = (float(*)[8][520])(sm + RING_FL);   // aliases Ds

    const int tid = threadIdx.x;
    const int lane = tid & 31, w = tid >> 5;
    const int wm = w >> 3, wn = w & 7;       // 2 x 8 warp grid
    const int qr = lane >> 2, qc = lane & 3;
    const int i0 = blockIdx.x * 64;

    const uint32_t sRing = (uint32_t)__cvta_generic_to_shared(ring);
    const uint32_t sDs   = (uint32_t)__cvta_generic_to_shared(sm + RING_FL);

    // loader indices
    const int lq_r = tid >> 3,  lq_c = (tid & 7) * 4;     // Q: 64 rows (tid<512 -> 1 ld)
    const int lk_r = tid >> 3,  lk_c = (tid & 7) * 4;     // K: 4 passes of 64 rows
    const int lv_r = tid >> 7,  lv_c = (tid & 127) * 4;   // V: 2 passes of 4 rows
    const int ld_r = tid >> 6,  ld_c = (tid & 63) * 4;    // D: tid<256 -> 4 rows/stage

    float o[2][8][4];
    #pragma unroll
    for (int f = 0; f < 2; f++)
        #pragma unroll
        for (int g = 0; g < 8; g++)
            #pragma unroll
            for (int e = 0; e < 4; e++) o[f][g][e] = 0.f;

    #pragma unroll 1
    for (int j0 = 0; j0 < NROWS; j0 += 256) {
        // ---- QK stage issue helper (stage kc into ring slot kc%3) ----
        // Q tile 64x32, K tile 256x32, D rows [4kc,4kc+4) x 256.
        auto issue_qk = [&](int kc) {
            uint32_t b = sRing + (uint32_t)((kc % 3) * STG_FL) * 4u;
            cpa16(b + (uint32_t)(lq_r*36 + lq_c)*4u,
                  &Q[(size_t)(i0 + lq_r)*DIM + kc*32 + lq_c]);
            #pragma unroll
            for (int p = 0; p < 4; p++) {
                int r = lk_r + p*64;
                cpa16(b + (uint32_t)(2304 + r*36 + lk_c)*4u,
                      &K[(size_t)(j0 + r)*DIM + kc*32 + lk_c]);
            }
            if (tid < 256) {
                int dr = kc*4 + ld_r;
                cpa16(sDs + (uint32_t)(dr*260 + ld_c)*4u,
                      &D[(size_t)(i0 + dr)*NROWS + j0 + ld_c]);
            }
            CPA_COMMIT();
        };

        issue_qk(0);
        issue_qk(1);

        float s[2][4][4];
        #pragma unroll
        for (int f = 0; f < 2; f++)
            #pragma unroll
            for (int g = 0; g < 4; g++)
                #pragma unroll
                for (int e = 0; e < 4; e++) s[f][g][e] = 0.f;

        // ---------------- QK:  S = Q @ K[j0:j0+256]^T ----------------
        #pragma unroll 1
        for (int kc = 0; kc < 16; kc++) {
            if (kc < 15) { CPA_WAIT1(); } else { CPA_WAIT0(); }
            __syncthreads();
            if (kc < 14) issue_qk(kc + 2);
            const float* Qs = ring + (kc % 3) * STG_FL;
            const float* Ks = Qs + 2304;
            #pragma unroll
            for (int k8 = 0; k8 < 4; k8++) {
                const int kk = k8*8 + qc;
                float a[2][4];
                #pragma unroll
                for (int f = 0; f < 2; f++) {
                    int rb = wm*32 + f*16 + qr;
                    a[f][0] = Qs[rb*36 + kk];       a[f][1] = Qs[(rb+8)*36 + kk];
                    a[f][2] = Qs[rb*36 + kk + 4];   a[f][3] = Qs[(rb+8)*36 + kk + 4];
                }
                #pragma unroll
                for (int g = 0; g < 4; g++) {
                    int nb = wn*32 + g*8 + qr;
                    float b[2] = { Ks[nb*36 + kk], Ks[nb*36 + kk + 4] };
                    mma8(s[0][g], a[0], b);
                    mma8(s[1][g], a[1], b);
                }
            }
        }
        __syncthreads();   // QK reads done -> Ss (aliases ring) may be written

        // ------- D-phase: Ss = tf32(S .* Ds)   (Ds already resident) -------
        #pragma unroll
        for (int f = 0; f < 2; f++)
            #pragma unroll
            for (int g = 0; g < 4; g++) {
                int r = wm*32 + f*16 + qr;
                int c = wn*32 + g*8 + 2*qc;
                float2 d0 = *(float2*)&Ds[r][c];
                float2 d1 = *(float2*)&Ds[r+8][c];
                *(float2*)&Ss[r][c]   = make_float2(tf32r(s[f][g][0]*d0.x),
                                                    tf32r(s[f][g][1]*d0.y));
                *(float2*)&Ss[r+8][c] = make_float2(tf32r(s[f][g][2]*d1.x),
                                                    tf32r(s[f][g][3]*d1.y));
            }
        __syncthreads();   // Ds reads done -> Vs (aliases Ds) may be written

        // ---- SV stage issue helper (stage st into Vs slot st%3) ----
        auto issue_v = [&](int st) {
            uint32_t b = sDs + (uint32_t)((st % 3) * 4160) * 4u;
            #pragma unroll
            for (int p = 0; p < 2; p++) {
                int r = lv_r + p*4;
                cpa16(b + (uint32_t)(r*520 + lv_c)*4u,
                      &V[(size_t)(j0 + st*8 + r)*DIM + lv_c]);
            }
            CPA_COMMIT();
        };

        issue_v(0);
        issue_v(1);

        // ------------- SV:  O += Ss @ V[j0:j0+256]  (32 stages) -------------
        #pragma unroll 1
        for (int st = 0; st < 32; st++) {
            if (st < 31) { CPA_WAIT1(); } else { CPA_WAIT0(); }
            __syncthreads();
            if (st < 30) issue_v(st + 2);
            const int b3 = st % 3;
            const int k = st*8 + qc;
            float a[2][4];
            #pragma unroll
            for (int f = 0; f < 2; f++) {
                int rb = wm*32 + f*16 + qr;
                a[f][0] = Ss[rb][k];     a[f][1] = Ss[rb+8][k];
                a[f][2] = Ss[rb][k+4];   a[f][3] = Ss[rb+8][k+4];
            }
            #pragma unroll
            for (int g = 0; g < 8; g++) {
                int n = wn*64 + g*8 + qr;
                float b[2] = { Vs[b3][qc][n], Vs[b3][qc+4][n] };
                mma8(o[0][g], a[0], b);
                mma8(o[1][g], a[1], b);
            }
        }
        __syncthreads();   // Ss/Vs reads done before next chunk's issues
    }

    // ---------------- epilogue ----------------
    #pragma unroll
    for (int f = 0; f < 2; f++)
        #pragma unroll
        for (int g = 0; g < 8; g++) {
            int r = i0 + wm*32 + f*16 + qr;
            int c = wn*64 + g*8 + 2*qc;
            *(float2*)&O[(size_t)r*DIM + c]       = make_float2(o[f][g][0], o[f][g][1]);
            *(float2*)&O[(size_t)(r + 8)*DIM + c] = make_float2(o[f][g][2], o[f][g][3]);
        }
}

// ===========================================================================
// Small GEMMs (tf32x3): C = act(A @ B + bias).  BM=128, BN=64, BK=32.
// 256 thr, warps 4(m) x 2(n), warp tile 32x32.  hi/lo split at SMEM store.
// ===========================================================================
#define GEMM_SMEM 55296

template<int ACT, int ROUND>
__global__ void __launch_bounds__(256) gemm_x3(
    const float* __restrict__ A, const float* __restrict__ B,
    const float* __restrict__ bias, float* __restrict__ C)
{
    extern __shared__ float sm[];
    float (*Ah)[36] = (float(*)[36]) sm;
    float (*Al)[36] = (float(*)[36])(sm + 4608);
    float (*Bh)[72] = (float(*)[72])(sm + 9216);
    float (*Bl)[72] = (float(*)[72])(sm + 11520);

    const int tid = threadIdx.x;
    const int lane = tid & 31, w = tid >> 5;
    const int wm = w >> 1, wn = w & 1;
    const int qr = lane >> 2, qc = lane & 3;
    const int bm = blockIdx.x * 128, bn = blockIdx.y * 64;

    float acc[2][4][4];
    #pragma unroll
    for (int f = 0; f < 2; f++)
        #pragma unroll
        for (int g = 0; g < 4; g++)
            #pragma unroll
            for (int e = 0; e < 4; e++) acc[f][g][e] = 0.f;

    float4 ap[4]; float4 bp[2];
    #pragma unroll
    for (int p = 0; p < 4; p++) {
        int idx = tid + p*256, r = idx >> 3, c4 = (idx & 7) * 4;
        ap[p] = *(const float4*)&A[(size_t)(bm + r)*DIM + c4];
    }
    #pragma unroll
    for (int p = 0; p < 2; p++) {
        int idx = tid + p*256, r = idx >> 4, c4 = (idx & 15) * 4;
        bp[p] = *(const float4*)&B[(size_t)r*DIM + bn + c4];
    }

    #pragma unroll 1
    for (int kc = 0; kc < 16; kc++) {
        #pragma unroll
        for (int p = 0; p < 4; p++) {
            int idx = tid + p*256, r = idx >> 3, c4 = (idx & 7) * 4;
            float vv[4] = {ap[p].x, ap[p].y, ap[p].z, ap[p].w};
            #pragma unroll
            for (int e = 0; e < 4; e++) {
                float h = tf32r(vv[e]);
                Ah[r][c4+e] = h;
                Al[r][c4+e] = tf32r(vv[e] - h);
            }
        }
        #pragma unroll
        for (int p = 0; p < 2; p++) {
            int idx = tid + p*256, r = idx >> 4, c4 = (idx & 15) * 4;
            float vv[4] = {bp[p].x, bp[p].y, bp[p].z, bp[p].w};
            #pragma unroll
            for (int e = 0; e < 4; e++) {
                float h = tf32r(vv[e]);
                Bh[r][c4+e] = h;
                Bl[r][c4+e] = tf32r(vv[e] - h);
            }
        }
        __syncthreads();
        if (kc < 15) {
            #pragma unroll
            for (int p = 0; p < 4; p++) {
                int idx = tid + p*256, r = idx >> 3, c4 = (idx & 7) * 4;
                ap[p] = *(const float4*)&A[(size_t)(bm + r)*DIM + (kc+1)*32 + c4];
            }
            #pragma unroll
            for (int p = 0; p < 2; p++) {
                int idx = tid + p*256, r = idx >> 4, c4 = (idx & 15) * 4;
                bp[p] = *(const float4*)&B[(size_t)((kc+1)*32 + r)*DIM + bn + c4];
            }
        }
        #pragma unroll
        for (int k8 = 0; k8 < 4; k8++) {
            const int kk = k8*8 + qc;
            float ah[2][4], al[2][4];
            #pragma unroll
            for (int f = 0; f < 2; f++) {
                int rb = wm*32 + f*16 + qr;
                ah[f][0] = Ah[rb][kk];   ah[f][1] = Ah[rb+8][kk];
                ah[f][2] = Ah[rb][kk+4]; ah[f][3] = Ah[rb+8][kk+4];
                al[f][0] = Al[rb][kk];   al[f][1] = Al[rb+8][kk];
                al[f][2] = Al[rb][kk+4]; al[f][3] = Al[rb+8][kk+4];
            }
            #pragma unroll
            for (int g = 0; g < 4; g++) {
                int n = wn*32 + g*8 + qr;
                float bh[2] = { Bh[kk][n], Bh[kk+4][n] };
                float bl[2] = { Bl[kk][n], Bl[kk+4][n] };
                #pragma unroll
                for (int f = 0; f < 2; f++) {
                    mma8(acc[f][g], ah[f], bh);
                    mma8(acc[f][g], al[f], bh);
                    mma8(acc[f][g], ah[f], bl);
                }
            }
        }
        __syncthreads();
    }

    #pragma unroll
    for (int f = 0; f < 2; f++)
        #pragma unroll
        for (int g = 0; g < 4; g++) {
            int r = bm + wm*32 + f*16 + qr;
            int c = bn + wn*32 + g*8 + 2*qc;
            float2 bb = *(const float2*)&bias[c];
            float v0 = acc[f][g][0] + bb.x, v1 = acc[f][g][1] + bb.y;
            float v2 = acc[f][g][2] + bb.x, v3 = acc[f][g][3] + bb.y;
            if (ACT == 1) {
                v0 = 0.5f*v0*(1.f + erff(v0*0.70710678118654752f));
                v1 = 0.5f*v1*(1.f + erff(v1*0.70710678118654752f));
                v2 = 0.5f*v2*(1.f + erff(v2*0.70710678118654752f));
                v3 = 0.5f*v3*(1.f + erff(v3*0.70710678118654752f));
            }
            if (ROUND == 1) { v0 = tf32r(v0); v1 = tf32r(v1); v2 = tf32r(v2); v3 = tf32r(v3); }
            *(float2*)&C[(size_t)r*DIM + c]       = make_float2(v0, v1);
            *(float2*)&C[(size_t)(r + 8)*DIM + c] = make_float2(v2, v3);
        }
}

// ---------------------------------------------------------------------------
__global__ void groupnorm_kernel(float* __restrict__ out,
                                 const float* __restrict__ gamma,
                                 const float* __restrict__ beta)
{
    __shared__ float buf[512];
    __shared__ float smu[16], siv[16];
    const int row = blockIdx.x;
    const int tid = threadIdx.x;
    float* p = out + (size_t)row * DIM;
    buf[tid]       = p[tid];
    buf[tid + 256] = p[tid + 256];
    __syncthreads();
    if (tid < 16) {
        float sx = 0.f, s2 = 0.f;
        #pragma unroll
        for (int c = 0; c < 32; c++) { float v = buf[tid*32 + c]; sx += v; s2 += v*v; }
        float mu  = sx * (1.f/32.f);
        float var = s2 * (1.f/32.f) - mu*mu;
        smu[tid] = mu;
        siv[tid] = rsqrtf(var + 1e-5f);
    }
    __syncthreads();
    #pragma unroll
    for (int q = 0; q < 2; q++) {
        int c = tid + q*256;
        int g = c >> 5;
        p[c] = (buf[c] - smu[g]) * siv[g] * gamma[c] + beta[c];
    }
}

// ---------------------------------------------------------------------------
extern "C" void kernel_launch(void* const* d_in, const int* in_sizes, int n_in,
                              void* d_out, int out_size)
{
    const float* x     = (const float*)d_in[0];
    const float* D     = (const float*)d_in[1];
    const float* Wq    = (const float*)d_in[2];
    const float* bq    = (const float*)d_in[3];
    const float* Wk    = (const float*)d_in[4];
    const float* bk    = (const float*)d_in[5];
    const float* Wv    = (const float*)d_in[6];
    const float* bv    = (const float*)d_in[7];
    const float* Wf    = (const float*)d_in[8];
    const float* bf    = (const float*)d_in[9];
    const float* Wp    = (const float*)d_in[10];
    const float* bp    = (const float*)d_in[11];
    const float* gamma = (const float*)d_in[12];
    const float* beta  = (const float*)d_in[13];
    float* out = (float*)d_out;

    float *Q, *K, *V, *XR, *H;
    cudaGetSymbolAddress((void**)&Q,  g_Q);
    cudaGetSymbolAddress((void**)&K,  g_K);
    cudaGetSymbolAddress((void**)&V,  g_V);
    cudaGetSymbolAddress((void**)&XR, g_XR);
    cudaGetSymbolAddress((void**)&H,  g_H);

    cudaFuncSetAttribute(gemm_x3<0,1>,
                         cudaFuncAttributeMaxDynamicSharedMemorySize, GEMM_SMEM);
    cudaFuncSetAttribute(gemm_x3<1,0>,
                         cudaFuncAttributeMaxDynamicSharedMemorySize, GEMM_SMEM);
    cudaFuncSetAttribute(gemm_x3<0,0>,
                         cudaFuncAttributeMaxDynamicSharedMemorySize, GEMM_SMEM);
    cudaFuncSetAttribute(retention_mma,
                         cudaFuncAttributeMaxDynamicSharedMemorySize, RET_SMEM);

    dim3 gs(NROWS/128, DIM/64);    // 64 x 8
    gemm_x3<0,1><<<gs, 256, GEMM_SMEM>>>(x, Wq, bq, Q);
    gemm_x3<0,1><<<gs, 256, GEMM_SMEM>>>(x, Wk, bk, K);
    gemm_x3<0,1><<<gs, 256, GEMM_SMEM>>>(x, Wv, bv, V);

    retention_mma<<<NROWS/64, 512, RET_SMEM>>>(Q, K, V, D, XR);

    gemm_x3<1,0><<<gs, 256, GEMM_SMEM>>>(XR, Wf, bf, H);   // exact GELU
    gemm_x3<0,0><<<gs, 256, GEMM_SMEM>>>(H,  Wp, bp, out);

    groupnorm_kernel<<<NROWS, 256>>>(out, gamma, beta);
}